// round 7
// baseline (speedup 1.0000x reference)
#include <cuda_runtime.h>
#include <cuda_bf16.h>
#include <cstdint>

// ---------------------------------------------------------------------------
// Transformer-XL masked MHA. S=1024, P=1024, J=2048, B=2, E=1024, H=16, I=64.
// All GEMMs + flash attention on mma.sync m16n8k16 bf16 (3-term split).
// PD stored pre-shifted in bf16; double-buffered GEMM smem.
// ---------------------------------------------------------------------------

constexpr int S_   = 1024;
constexpr int P_   = 1024;
constexpr int B_   = 2;
constexpr int E_   = 1024;
constexpr int H_   = 16;
constexpr int I_   = 64;
constexpr int J_   = 2048;
constexpr int HI_  = 1024;
constexpr float SCALE_ = 0.125f;
constexpr float EPS_   = 1e-5f;

// ------------------------- scratch (device globals) ------------------------
__device__ __nv_bfloat16 g_Khi [(size_t)B_*H_*J_*I_];  // [bh][j][i]
__device__ __nv_bfloat16 g_Klo [(size_t)B_*H_*J_*I_];
__device__ __nv_bfloat16 g_Vthi[(size_t)B_*H_*I_*J_];  // [bh][i][j] (transposed)
__device__ __nv_bfloat16 g_Vtlo[(size_t)B_*H_*I_*J_];
__device__ __nv_bfloat16 g_quhi[(size_t)B_*H_*S_*I_];  // [bh][s][i]
__device__ __nv_bfloat16 g_qulo[(size_t)B_*H_*S_*I_];
__device__ float g_qv  [(size_t)B_*H_*S_*I_];
__device__ float g_pos [(size_t)H_*J_*I_];
__device__ __nv_bfloat16 g_PD [(size_t)B_*H_*S_*J_];   // pre-shifted [bh][s][j]
__device__ float g_ctx [(size_t)S_*B_*HI_];
__device__ float g_proj[(size_t)S_*B_*E_];

// ------------------------------ split helpers ------------------------------
__device__ __forceinline__ void split1(float x, __nv_bfloat16& h, __nv_bfloat16& l) {
    h = __float2bfloat16(x);
    l = __float2bfloat16(x - __bfloat162float(h));
}
__device__ __forceinline__ void split2(float x, float y,
                                       uint32_t& hi, uint32_t& lo) {
    __nv_bfloat162 h = __floats2bfloat162_rn(x, y);
    __nv_bfloat162 l = __floats2bfloat162_rn(x - __bfloat162float(h.x),
                                             y - __bfloat162float(h.y));
    hi = *(const uint32_t*)&h;
    lo = *(const uint32_t*)&l;
}
__device__ __forceinline__ void mma_bf16(float* d, const uint32_t* a,
                                         const uint32_t* b) {
    asm volatile(
        "mma.sync.aligned.m16n8k16.row.col.f32.bf16.bf16.f32 "
        "{%0,%1,%2,%3}, {%4,%5,%6,%7}, {%8,%9}, {%0,%1,%2,%3};"
        : "+f"(d[0]), "+f"(d[1]), "+f"(d[2]), "+f"(d[3])
        : "r"(a[0]), "r"(a[1]), "r"(a[2]), "r"(a[3]), "r"(b[0]), "r"(b[1]));
}

// ------------------------------- functors ----------------------------------
struct ALoadKV {
    const float* mem; const float* x;
    __device__ __forceinline__ float4 operator()(int, int m, int k) const {
        const float* p = (m < P_*B_) ? (mem + (size_t)m*E_ + k)
                                     : (x + (size_t)(m - P_*B_)*E_ + k);
        return *(const float4*)p;
    }
};
struct ALoadPlain {
    const float* a; int K;
    __device__ __forceinline__ float4 operator()(int, int m, int k) const {
        return *(const float4*)(a + (size_t)m*K + k);
    }
};
struct ALoadQV {
    __device__ __forceinline__ float4 operator()(int bz, int m, int k) const {
        return *(const float4*)&g_qv[((size_t)bz*S_ + m)*I_ + k];
    }
};
struct ALoadCtx {
    __device__ __forceinline__ float4 operator()(int, int m, int k) const {
        return *(const float4*)&g_ctx[(size_t)m*HI_ + k];
    }
};
struct BLoadW {
    const float* w; int K;
    __device__ __forceinline__ float4 operator()(int, int n, int k) const {
        return *(const float4*)(w + (size_t)n*K + k);
    }
};
struct BLoadPos {
    __device__ __forceinline__ float4 operator()(int bz, int n, int k) const {
        return *(const float4*)&g_pos[((size_t)(bz % H_)*J_ + n)*I_ + k];
    }
};

struct CStoreKV {
    static constexpr bool kSkipPD = false;
    __device__ __forceinline__ void operator()(int, int m, int n, float c) const {
        int j = m / B_, b = m % B_;
        __nv_bfloat16 h, l;
        split1(c, h, l);
        if (n < HI_) {
            int hh = n >> 6, i = n & 63;
            size_t o = (((size_t)(b*H_ + hh))*J_ + j)*I_ + i;
            g_Khi[o] = h; g_Klo[o] = l;
        } else {
            int n2 = n - HI_; int hh = n2 >> 6, i = n2 & 63;
            size_t o = (((size_t)(b*H_ + hh))*I_ + i)*J_ + j;  // transposed
            g_Vthi[o] = h; g_Vtlo[o] = l;
        }
    }
};
struct CStoreQ {
    static constexpr bool kSkipPD = false;
    const float* u; const float* v;
    __device__ __forceinline__ void operator()(int, int m, int n, float c) const {
        int s = m / B_, b = m % B_;
        int hh = n >> 6, i = n & 63;
        size_t o = (((size_t)(b*H_ + hh))*S_ + s)*I_ + i;
        float qu = c + u[n];
        __nv_bfloat16 h, l;
        split1(qu, h, l);
        g_quhi[o] = h; g_qulo[o] = l;
        g_qv[o] = c + v[n];
    }
};
struct CStorePos {
    static constexpr bool kSkipPD = false;
    __device__ __forceinline__ void operator()(int, int m, int n, float c) const {
        int hh = n >> 6, i = n & 63;
        g_pos[((size_t)hh*J_ + m)*I_ + i] = c;
    }
};
struct CStorePD {
    static constexpr bool kSkipPD = true;   // tiles with m0+n0<=768 fully dropped
    __device__ __forceinline__ void operator()(int bz, int m, int n, float c) const {
        int j = n + m - 1023;
        if (j >= 0) g_PD[((size_t)bz*S_ + m)*J_ + j] = __float2bfloat16(c);
    }
};
struct CStoreProj {
    static constexpr bool kSkipPD = false;
    const float* x;
    __device__ __forceinline__ void operator()(int, int m, int n, float c) const {
        g_proj[(size_t)m*E_ + n] = c + x[(size_t)m*E_ + n];
    }
};

// ------------------------- mma.sync GEMM (split-bf16) ----------------------
// C[m,n] = sum_k A[m,k]*B[n,k]. 128x128 block tile, BK=32, 8 warps (2x4),
// warp tile 64x32, m16n8k16 bf16 MMA, 3-term split: Ah*Bh + Ah*Bl + Al*Bh.
// Double-buffered dynamic smem, one __syncthreads per chunk.
constexpr int SROW = 40;           // bf16 per smem row (32 data + 8 pad)
constexpr int TSZ  = 128 * SROW;   // elems per operand array
constexpr int GEMM_SMEM = 2 * 4 * TSZ * 2;   // 2 buffers x 4 arrays x TSZ x 2B

template<class AL, class BL, class CS>
__global__ void __launch_bounds__(256)
gemm_mma(AL aload, BL bload, CS cstore, int K) {
    extern __shared__ __nv_bfloat16 gsm[];

    const int tid  = threadIdx.x;
    const int wid  = tid >> 5;
    const int lane = tid & 31;
    const int gid  = lane >> 2;
    const int tig  = lane & 3;
    const int wm   = wid >> 2;
    const int wn   = wid & 3;
    const int m0   = blockIdx.y * 128;
    const int n0   = blockIdx.x * 128;
    const int bz   = blockIdx.z;

    if constexpr (CS::kSkipPD) {
        if (m0 + n0 <= 768) return;   // all j = n+m-1023 < 0 -> nothing to do
    }

    const int frow = tid >> 1;            // 0..127  (row loaded by this thread)
    const int fkq  = (tid & 1) * 4;       // 0 or 4  (base k of float4 pair)

    float c[4][4][4];
#pragma unroll
    for (int mt = 0; mt < 4; mt++)
#pragma unroll
        for (int nt = 0; nt < 4; nt++)
#pragma unroll
            for (int r = 0; r < 4; r++) c[mt][nt][r] = 0.f;

    float4 av[4], bv[4];
    // each thread loads 4 float4s: rows frow, k = fkq + {0,8,16,24}
#pragma unroll
    for (int q = 0; q < 4; q++) {
        av[q] = aload(bz, m0 + frow, fkq + q * 8);
        bv[q] = bload(bz, n0 + frow, fkq + q * 8);
    }
    // store chunk 0 into buffer 0
    {
        __nv_bfloat16* buf = gsm;
#pragma unroll
        for (int q = 0; q < 4; q++) {
            const int so = frow * SROW + fkq + q * 8;
            uint32_t h0, l0, h1, l1;
            split2(av[q].x, av[q].y, h0, l0);
            split2(av[q].z, av[q].w, h1, l1);
            *(uint2*)&buf[so]           = make_uint2(h0, h1);
            *(uint2*)&buf[TSZ + so]     = make_uint2(l0, l1);
            split2(bv[q].x, bv[q].y, h0, l0);
            split2(bv[q].z, bv[q].w, h1, l1);
            *(uint2*)&buf[2*TSZ + so]   = make_uint2(h0, h1);
            *(uint2*)&buf[3*TSZ + so]   = make_uint2(l0, l1);
        }
    }

    const int nc = K >> 5;
    for (int ch = 0; ch < nc; ch++) {
        const bool more = (ch + 1 < nc);
        if (more) {
#pragma unroll
            for (int q = 0; q < 4; q++) {
                av[q] = aload(bz, m0 + frow, (ch + 1) * 32 + fkq + q * 8);
                bv[q] = bload(bz, n0 + frow, (ch + 1) * 32 + fkq + q * 8);
            }
        }
        __syncthreads();   // chunk ch's smem visible; buf[(ch+1)&1] free

        const __nv_bfloat16* buf = gsm + (ch & 1) * 4 * TSZ;
        const __nv_bfloat16* sA0 = buf;
        const __nv_bfloat16* sA1 = buf + TSZ;
        const __nv_bfloat16* sB0 = buf + 2 * TSZ;
        const __nv_bfloat16* sB1 = buf + 3 * TSZ;

#pragma unroll
        for (int ks = 0; ks < 2; ks++) {
            const int kk = ks * 16 + tig * 2;
            uint32_t ah[4][4], al[4][4];
#pragma unroll
            for (int mt = 0; mt < 4; mt++) {
                const int m = wm * 64 + mt * 16 + gid;
                ah[mt][0] = *(const uint32_t*)&sA0[m * SROW + kk];
                ah[mt][1] = *(const uint32_t*)&sA0[(m + 8) * SROW + kk];
                ah[mt][2] = *(const uint32_t*)&sA0[m * SROW + kk + 8];
                ah[mt][3] = *(const uint32_t*)&sA0[(m + 8) * SROW + kk + 8];
                al[mt][0] = *(const uint32_t*)&sA1[m * SROW + kk];
                al[mt][1] = *(const uint32_t*)&sA1[(m + 8) * SROW + kk];
                al[mt][2] = *(const uint32_t*)&sA1[m * SROW + kk + 8];
                al[mt][3] = *(const uint32_t*)&sA1[(m + 8) * SROW + kk + 8];
            }
#pragma unroll
            for (int nt = 0; nt < 4; nt++) {
                const int n = wn * 32 + nt * 8 + gid;
                uint32_t bh[2], bl[2];
                bh[0] = *(const uint32_t*)&sB0[n * SROW + kk];
                bh[1] = *(const uint32_t*)&sB0[n * SROW + kk + 8];
                bl[0] = *(const uint32_t*)&sB1[n * SROW + kk];
                bl[1] = *(const uint32_t*)&sB1[n * SROW + kk + 8];
#pragma unroll
                for (int mt = 0; mt < 4; mt++) {
                    mma_bf16(c[mt][nt], ah[mt], bh);
                    mma_bf16(c[mt][nt], ah[mt], bl);
                    mma_bf16(c[mt][nt], al[mt], bh);
                }
            }
        }

        if (more) {
            __nv_bfloat16* nbuf = gsm + ((ch + 1) & 1) * 4 * TSZ;
#pragma unroll
            for (int q = 0; q < 4; q++) {
                const int so = frow * SROW + fkq + q * 8;
                uint32_t h0, l0, h1, l1;
                split2(av[q].x, av[q].y, h0, l0);
                split2(av[q].z, av[q].w, h1, l1);
                *(uint2*)&nbuf[so]         = make_uint2(h0, h1);
                *(uint2*)&nbuf[TSZ + so]   = make_uint2(l0, l1);
                split2(bv[q].x, bv[q].y, h0, l0);
                split2(bv[q].z, bv[q].w, h1, l1);
                *(uint2*)&nbuf[2*TSZ + so] = make_uint2(h0, h1);
                *(uint2*)&nbuf[3*TSZ + so] = make_uint2(l0, l1);
            }
        }
    }

#pragma unroll
    for (int mt = 0; mt < 4; mt++) {
        const int gm = m0 + wm * 64 + mt * 16 + gid;
#pragma unroll
        for (int nt = 0; nt < 4; nt++) {
            const int gn = n0 + wn * 32 + nt * 8 + tig * 2;
            cstore(bz, gm,     gn,     c[mt][nt][0]);
            cstore(bz, gm,     gn + 1, c[mt][nt][1]);
            cstore(bz, gm + 8, gn,     c[mt][nt][2]);
            cstore(bz, gm + 8, gn + 1, c[mt][nt][3]);
        }
    }
}

// ---------------------------- flash attention (MMA) ------------------------
// grid (S/128, B*H), 256 threads = 8 warps; warp wq owns rows wq*16..+15.
// j-tiles of 64. Q/K/Vt pre-split bf16 in gmem; PD bf16 read into fragments.
constexpr int FPAD = 72;   // bf16 elems per smem row (64 data + 8 pad) = 36 words
constexpr int FLASH_SMEM = (128 + 64 + 64) * FPAD * 2 * 2;  // 73728 B

__global__ void __launch_bounds__(256) flash_mma() {
    extern __shared__ __nv_bfloat16 fsm[];
    __nv_bfloat16* sQh = fsm;                    // [s][i] 128x72
    __nv_bfloat16* sQl = sQh + 128 * FPAD;
    __nv_bfloat16* sKh = sQl + 128 * FPAD;       // [j][i] 64x72
    __nv_bfloat16* sKl = sKh + 64 * FPAD;
    __nv_bfloat16* sVh = sKl + 64 * FPAD;        // [i][j] 64x72
    __nv_bfloat16* sVl = sVh + 64 * FPAD;

    const int tid  = threadIdx.x;
    const int wq   = tid >> 5;
    const int lane = tid & 31;
    const int gid  = lane >> 2;
    const int tig  = lane & 3;
    const int s0   = blockIdx.x * 128;
    const int bh   = blockIdx.y;

    const int s_r0 = s0 + wq * 16 + gid;
    const int s_r1 = s_r0 + 8;

    // ---- load Q tile (rows s0..s0+127, 32 words each) ----
    {
        const int row  = tid >> 1;
        const int half = (tid & 1) * 16;                       // word offset
        const uint4* srch = (const uint4*)((const uint32_t*)
            (g_quhi + ((size_t)bh * S_ + s0 + row) * I_) + half);
        const uint4* srcl = (const uint4*)((const uint32_t*)
            (g_qulo + ((size_t)bh * S_ + s0 + row) * I_) + half);
        uint4* dsth = (uint4*)((uint32_t*)&sQh[row * FPAD] + half);
        uint4* dstl = (uint4*)((uint32_t*)&sQl[row * FPAD] + half);
#pragma unroll
        for (int q = 0; q < 4; q++) { dsth[q] = srch[q]; dstl[q] = srcl[q]; }
    }

    const __nv_bfloat16* PDb = g_PD + (size_t)bh * S_ * J_;

    float m_[2] = {-3.0e38f, -3.0e38f};
    float l_[2] = {0.f, 0.f};
    float o[8][4];
#pragma unroll
    for (int nt = 0; nt < 8; nt++)
#pragma unroll
        for (int r = 0; r < 4; r++) o[nt][r] = 0.f;

    const int ntiles = min(32, s0 / 64 + 18);
    for (int jt = 0; jt < ntiles; jt++) {
        const int j0 = jt * 64;
        __syncthreads();
        // ---- load K [j][i] and Vt [i][j] tiles (64 rows x 32 words) ----
        {
            const int row = tid >> 2;
            const int qw  = (tid & 3) * 8;                     // word offset
            const uint32_t* kh = (const uint32_t*)
                (g_Khi + (((size_t)bh * J_) + j0 + row) * I_) + qw;
            const uint32_t* kl = (const uint32_t*)
                (g_Klo + (((size_t)bh * J_) + j0 + row) * I_) + qw;
            const uint32_t* vh = (const uint32_t*)
                (g_Vthi + ((size_t)bh * I_ + row) * J_ + j0) + qw;
            const uint32_t* vl = (const uint32_t*)
                (g_Vtlo + ((size_t)bh * I_ + row) * J_ + j0) + qw;
            uint32_t* dkh = (uint32_t*)&sKh[row * FPAD] + qw;
            uint32_t* dkl = (uint32_t*)&sKl[row * FPAD] + qw;
            uint32_t* dvh = (uint32_t*)&sVh[row * FPAD] + qw;
            uint32_t* dvl = (uint32_t*)&sVl[row * FPAD] + qw;
            *(uint4*)dkh = *(const uint4*)kh;  *(uint4*)(dkh+4) = *(const uint4*)(kh+4);
            *(uint4*)dkl = *(const uint4*)kl;  *(uint4*)(dkl+4) = *(const uint4*)(kl+4);
            *(uint4*)dvh = *(const uint4*)vh;  *(uint4*)(dvh+4) = *(const uint4*)(vh+4);
            *(uint4*)dvl = *(const uint4*)vl;  *(uint4*)(dvl+4) = *(const uint4*)(vl+4);
        }
        __syncthreads();

        // ---- scores S = Q @ K^T (128x64 per block, 16x64 per warp) ----
        float sc[8][4];
#pragma unroll
        for (int nt = 0; nt < 8; nt++)
#pragma unroll
            for (int r = 0; r < 4; r++) sc[nt][r] = 0.f;

        const uint32_t* qh32 = (const uint32_t*)sQh;
        const uint32_t* ql32 = (const uint32_t*)sQl;
        const uint32_t* kh32 = (const uint32_t*)sKh;
        const uint32_t* kl32 = (const uint32_t*)sKl;
        const int r0w = (wq * 16 + gid) * (FPAD/2);
        const int r1w = r0w + 8 * (FPAD/2);
#pragma unroll
        for (int ks = 0; ks < 4; ks++) {
            const int w = ks * 8 + tig;
            uint32_t ah[4], al[4];
            ah[0] = qh32[r0w + w];     ah[1] = qh32[r1w + w];
            ah[2] = qh32[r0w + w + 4]; ah[3] = qh32[r1w + w + 4];
            al[0] = ql32[r0w + w];     al[1] = ql32[r1w + w];
            al[2] = ql32[r0w + w + 4]; al[3] = ql32[r1w + w + 4];
#pragma unroll
            for (int nt = 0; nt < 8; nt++) {
                const int nw = (nt * 8 + gid) * (FPAD/2);
                uint32_t bh2[2] = { kh32[nw + w], kh32[nw + w + 4] };
                uint32_t bl2[2] = { kl32[nw + w], kl32[nw + w + 4] };
                mma_bf16(sc[nt], ah, bh2);
                mma_bf16(sc[nt], ah, bl2);
                mma_bf16(sc[nt], al, bh2);
            }
        }

        // ---- + PD (bf16), mask, scale ----
#pragma unroll
        for (int nt = 0; nt < 8; nt++) {
            const int jc = j0 + nt * 8 + tig * 2;
            __nv_bfloat162 p0 = *(const __nv_bfloat162*)&PDb[(size_t)s_r0 * J_ + jc];
            __nv_bfloat162 p1 = *(const __nv_bfloat162*)&PDb[(size_t)s_r1 * J_ + jc];
            sc[nt][0] = (jc     <= s_r0 + P_)
                        ? (sc[nt][0] + __bfloat162float(p0.x)) * SCALE_ : -1.0e30f;
            sc[nt][1] = (jc + 1 <= s_r0 + P_)
                        ? (sc[nt][1] + __bfloat162float(p0.y)) * SCALE_ : -1.0e30f;
            sc[nt][2] = (jc     <= s_r1 + P_)
                        ? (sc[nt][2] + __bfloat162float(p1.x)) * SCALE_ : -1.0e30f;
            sc[nt][3] = (jc + 1 <= s_r1 + P_)
                        ? (sc[nt][3] + __bfloat162float(p1.y)) * SCALE_ : -1.0e30f;
        }

        // ---- online softmax (rows r0: idx 0,1; r1: idx 2,3) ----
#pragma unroll
        for (int h = 0; h < 2; h++) {
            float mx = -3.0e38f;
#pragma unroll
            for (int nt = 0; nt < 8; nt++)
                mx = fmaxf(mx, fmaxf(sc[nt][2*h], sc[nt][2*h+1]));
            mx = fmaxf(mx, __shfl_xor_sync(0xffffffffu, mx, 1));
            mx = fmaxf(mx, __shfl_xor_sync(0xffffffffu, mx, 2));
            const float m_new = fmaxf(m_[h], mx);
            const float corr  = __expf(m_[h] - m_new);
            float sum = 0.f;
#pragma unroll
            for (int nt = 0; nt < 8; nt++) {
                float p0 = __expf(sc[nt][2*h]   - m_new);
                float p1 = __expf(sc[nt][2*h+1] - m_new);
                sc[nt][2*h] = p0; sc[nt][2*h+1] = p1;
                sum += p0 + p1;
            }
            sum += __shfl_xor_sync(0xffffffffu, sum, 1);
            sum += __shfl_xor_sync(0xffffffffu, sum, 2);
            l_[h] = l_[h] * corr + sum;
            m_[h] = m_new;
#pragma unroll
            for (int nt = 0; nt < 8; nt++) {
                o[nt][2*h]   *= corr;
                o[nt][2*h+1] *= corr;
            }
        }

        // ---- O += P @ V (P fragments from scores, V^T as B) ----
        const uint32_t* vh32 = (const uint32_t*)sVh;
        const uint32_t* vl32 = (const uint32_t*)sVl;
#pragma unroll
        for (int ks = 0; ks < 4; ks++) {
            uint32_t ph[4], pl[4];
            split2(sc[2*ks][0],   sc[2*ks][1],   ph[0], pl[0]);
            split2(sc[2*ks][2],   sc[2*ks][3],   ph[1], pl[1]);
            split2(sc[2*ks+1][0], sc[2*ks+1][1], ph[2], pl[2]);
            split2(sc[2*ks+1][2], sc[2*ks+1][3], ph[3], pl[3]);
            const int w = ks * 8 + tig;
#pragma unroll
            for (int nt = 0; nt < 8; nt++) {
                const int nw = (nt * 8 + gid) * (FPAD/2);
                uint32_t bh2[2] = { vh32[nw + w], vh32[nw + w + 4] };
                uint32_t bl2[2] = { vl32[nw + w], vl32[nw + w + 4] };
                mma_bf16(o[nt], ph, bh2);
                mma_bf16(o[nt], ph, bl2);
                mma_bf16(o[nt], pl, bh2);
            }
        }
    }

    // ---- epilogue: ctx[(s,b)][h*64+i] ----
    const float inv0 = 1.f / l_[0];
    const float inv1 = 1.f / l_[1];
    const int b = bh >> 4, hh = bh & 15;
#pragma unroll
    for (int nt = 0; nt < 8; nt++) {
        const int ic = hh * 64 + nt * 8 + tig * 2;
        *(float2*)&g_ctx[((size_t)(s_r0 * B_ + b)) * HI_ + ic] =
            make_float2(o[nt][0] * inv0, o[nt][1] * inv0);
        *(float2*)&g_ctx[((size_t)(s_r1 * B_ + b)) * HI_ + ic] =
            make_float2(o[nt][2] * inv1, o[nt][3] * inv1);
    }
}

// ------------------------------ layernorm ----------------------------------
__device__ __forceinline__ float warp_red_sum(float v) {
#pragma unroll
    for (int o = 16; o; o >>= 1) v += __shfl_xor_sync(0xffffffffu, v, o);
    return v;
}
__global__ void __launch_bounds__(256)
ln_kernel(const float* __restrict__ gamma, const float* __restrict__ beta,
          float* __restrict__ out) {
    const int row = blockIdx.x;
    const int tid = threadIdx.x;
    const float* p = g_proj + (size_t)row * E_;
    __shared__ float red[8];

    float v[4];
    float s = 0.f;
#pragma unroll
    for (int t = 0; t < 4; t++) { v[t] = p[tid + t*256]; s += v[t]; }
    s = warp_red_sum(s);
    if ((tid & 31) == 0) red[tid >> 5] = s;
    __syncthreads();
    float tot = 0.f;
#pragma unroll
    for (int w = 0; w < 8; w++) tot += red[w];
    const float mu = tot * (1.0f / E_);

    float vs = 0.f;
#pragma unroll
    for (int t = 0; t < 4; t++) { float d = v[t] - mu; vs += d * d; }
    vs = warp_red_sum(vs);
    __syncthreads();
    if ((tid & 31) == 0) red[tid >> 5] = vs;
    __syncthreads();
    float vtot = 0.f;
#pragma unroll
    for (int w = 0; w < 8; w++) vtot += red[w];
    const float inv = rsqrtf(vtot * (1.0f / E_) + EPS_);

#pragma unroll
    for (int t = 0; t < 4; t++) {
        int e = tid + t*256;
        out[(size_t)row * E_ + e] = (v[t] - mu) * inv * gamma[e] + beta[e];
    }
}

// ------------------------------- launch ------------------------------------
extern "C" void kernel_launch(void* const* d_in, const int* in_sizes, int n_in,
                              void* d_out, int out_size) {
    (void)in_sizes; (void)n_in; (void)out_size;
    const float* x     = (const float*)d_in[0];
    const float* rel   = (const float*)d_in[1];
    const float* mem   = (const float*)d_in[2];
    const float* u     = (const float*)d_in[3];
    const float* v     = (const float*)d_in[4];
    const float* Wkv   = (const float*)d_in[6];
    const float* Wq    = (const float*)d_in[7];
    const float* Wp    = (const float*)d_in[8];
    const float* Wo    = (const float*)d_in[9];
    const float* gamma = (const float*)d_in[10];
    const float* beta  = (const float*)d_in[11];
    float* out = (float*)d_out;

    // unconditional (no static guards); attribute calls are capture-safe
    cudaFuncSetAttribute(flash_mma,
                         cudaFuncAttributeMaxDynamicSharedMemorySize, FLASH_SMEM);
    cudaFuncSetAttribute(gemm_mma<ALoadKV, BLoadW, CStoreKV>,
                         cudaFuncAttributeMaxDynamicSharedMemorySize, GEMM_SMEM);
    cudaFuncSetAttribute(gemm_mma<ALoadPlain, BLoadW, CStoreQ>,
                         cudaFuncAttributeMaxDynamicSharedMemorySize, GEMM_SMEM);
    cudaFuncSetAttribute(gemm_mma<ALoadPlain, BLoadW, CStorePos>,
                         cudaFuncAttributeMaxDynamicSharedMemorySize, GEMM_SMEM);
    cudaFuncSetAttribute(gemm_mma<ALoadQV, BLoadPos, CStorePD>,
                         cudaFuncAttributeMaxDynamicSharedMemorySize, GEMM_SMEM);
    cudaFuncSetAttribute(gemm_mma<ALoadCtx, BLoadW, CStoreProj>,
                         cudaFuncAttributeMaxDynamicSharedMemorySize, GEMM_SMEM);

    // 1. kv projection -> Khi/Klo, Vthi/Vtlo (split bf16, V transposed)
    gemm_mma<<<dim3(2*HI_/128, J_*B_/128, 1), 256, GEMM_SMEM>>>(
        ALoadKV{mem, x}, BLoadW{Wkv, E_}, CStoreKV{}, E_);

    // 2. q projection -> quhi/qulo (+u), qv fp32 (+v)
    gemm_mma<<<dim3(HI_/128, S_*B_/128, 1), 256, GEMM_SMEM>>>(
        ALoadPlain{x, E_}, BLoadW{Wq, E_}, CStoreQ{u, v}, E_);

    // 3. pos projection (fp32)
    gemm_mma<<<dim3(HI_/128, J_/128, 1), 256, GEMM_SMEM>>>(
        ALoadPlain{rel, E_}, BLoadW{Wp, E_}, CStorePos{}, E_);

    // 4. PD (pre-shifted store, bf16, early-exit on fully-dropped tiles)
    gemm_mma<<<dim3(J_/128, S_/128, B_*H_), 256, GEMM_SMEM>>>(
        ALoadQV{}, BLoadPos{}, CStorePD{}, I_);

    // 5. flash attention (tensor cores) -> ctx
    flash_mma<<<dim3(S_/128, B_*H_), 256, FLASH_SMEM>>>();

    // 6. out projection + residual
    gemm_mma<<<dim3(E_/128, S_*B_/128, 1), 256, GEMM_SMEM>>>(
        ALoadCtx{}, BLoadW{Wo, HI_}, CStoreProj{x}, HI_);

    // 7. layernorm
    ln_kernel<<<S_*B_, 256>>>(gamma, beta, out);
}

// round 8
// speedup vs baseline: 1.1281x; 1.1281x over previous
#include <cuda_runtime.h>
#include <cuda_bf16.h>
#include <cstdint>

// ---------------------------------------------------------------------------
// Transformer-XL masked MHA. S=1024, P=1024, J=2048, B=2, E=1024, H=16, I=64.
// All GEMMs + flash attention on mma.sync m16n8k16 bf16 (3-term split).
// GEMM core = Round-6 schedule (measured best). PD in bf16 + tile early-exit.
// ---------------------------------------------------------------------------

constexpr int S_   = 1024;
constexpr int P_   = 1024;
constexpr int B_   = 2;
constexpr int E_   = 1024;
constexpr int H_   = 16;
constexpr int I_   = 64;
constexpr int J_   = 2048;
constexpr int HI_  = 1024;
constexpr float SCALE_ = 0.125f;
constexpr float EPS_   = 1e-5f;

// ------------------------- scratch (device globals) ------------------------
__device__ __nv_bfloat16 g_Khi [(size_t)B_*H_*J_*I_];  // [bh][j][i]
__device__ __nv_bfloat16 g_Klo [(size_t)B_*H_*J_*I_];
__device__ __nv_bfloat16 g_Vthi[(size_t)B_*H_*I_*J_];  // [bh][i][j] (transposed)
__device__ __nv_bfloat16 g_Vtlo[(size_t)B_*H_*I_*J_];
__device__ __nv_bfloat16 g_quhi[(size_t)B_*H_*S_*I_];  // [bh][s][i]
__device__ __nv_bfloat16 g_qulo[(size_t)B_*H_*S_*I_];
__device__ float g_qv  [(size_t)B_*H_*S_*I_];
__device__ float g_pos [(size_t)H_*J_*I_];
__device__ __nv_bfloat16 g_PD [(size_t)B_*H_*S_*J_];   // pre-shifted [bh][s][j]
__device__ float g_ctx [(size_t)S_*B_*HI_];
__device__ float g_proj[(size_t)S_*B_*E_];

// ------------------------------ split helpers ------------------------------
__device__ __forceinline__ void split1(float x, __nv_bfloat16& h, __nv_bfloat16& l) {
    h = __float2bfloat16(x);
    l = __float2bfloat16(x - __bfloat162float(h));
}
__device__ __forceinline__ void split2(float x, float y,
                                       uint32_t& hi, uint32_t& lo) {
    __nv_bfloat162 h = __floats2bfloat162_rn(x, y);
    __nv_bfloat162 l = __floats2bfloat162_rn(x - __bfloat162float(h.x),
                                             y - __bfloat162float(h.y));
    hi = *(const uint32_t*)&h;
    lo = *(const uint32_t*)&l;
}
__device__ __forceinline__ void mma_bf16(float* d, const uint32_t* a,
                                         const uint32_t* b) {
    asm volatile(
        "mma.sync.aligned.m16n8k16.row.col.f32.bf16.bf16.f32 "
        "{%0,%1,%2,%3}, {%4,%5,%6,%7}, {%8,%9}, {%0,%1,%2,%3};"
        : "+f"(d[0]), "+f"(d[1]), "+f"(d[2]), "+f"(d[3])
        : "r"(a[0]), "r"(a[1]), "r"(a[2]), "r"(a[3]), "r"(b[0]), "r"(b[1]));
}

// ------------------------------- functors ----------------------------------
struct ALoadKV {
    const float* mem; const float* x;
    __device__ __forceinline__ float4 operator()(int, int m, int k) const {
        const float* p = (m < P_*B_) ? (mem + (size_t)m*E_ + k)
                                     : (x + (size_t)(m - P_*B_)*E_ + k);
        return *(const float4*)p;
    }
};
struct ALoadPlain {
    const float* a; int K;
    __device__ __forceinline__ float4 operator()(int, int m, int k) const {
        return *(const float4*)(a + (size_t)m*K + k);
    }
};
struct ALoadQV {
    __device__ __forceinline__ float4 operator()(int bz, int m, int k) const {
        return *(const float4*)&g_qv[((size_t)bz*S_ + m)*I_ + k];
    }
};
struct ALoadCtx {
    __device__ __forceinline__ float4 operator()(int, int m, int k) const {
        return *(const float4*)&g_ctx[(size_t)m*HI_ + k];
    }
};
struct BLoadW {
    const float* w; int K;
    __device__ __forceinline__ float4 operator()(int, int n, int k) const {
        return *(const float4*)(w + (size_t)n*K + k);
    }
};
struct BLoadPos {
    __device__ __forceinline__ float4 operator()(int bz, int n, int k) const {
        return *(const float4*)&g_pos[((size_t)(bz % H_)*J_ + n)*I_ + k];
    }
};

struct CStoreKV {
    static constexpr bool kSkipPD = false;
    __device__ __forceinline__ void operator()(int, int m, int n, float c) const {
        int j = m / B_, b = m % B_;
        __nv_bfloat16 h, l;
        split1(c, h, l);
        if (n < HI_) {
            int hh = n >> 6, i = n & 63;
            size_t o = (((size_t)(b*H_ + hh))*J_ + j)*I_ + i;
            g_Khi[o] = h; g_Klo[o] = l;
        } else {
            int n2 = n - HI_; int hh = n2 >> 6, i = n2 & 63;
            size_t o = (((size_t)(b*H_ + hh))*I_ + i)*J_ + j;  // transposed
            g_Vthi[o] = h; g_Vtlo[o] = l;
        }
    }
};
struct CStoreQ {
    static constexpr bool kSkipPD = false;
    const float* u; const float* v;
    __device__ __forceinline__ void operator()(int, int m, int n, float c) const {
        int s = m / B_, b = m % B_;
        int hh = n >> 6, i = n & 63;
        size_t o = (((size_t)(b*H_ + hh))*S_ + s)*I_ + i;
        float qu = c + u[n];
        __nv_bfloat16 h, l;
        split1(qu, h, l);
        g_quhi[o] = h; g_qulo[o] = l;
        g_qv[o] = c + v[n];
    }
};
struct CStorePos {
    static constexpr bool kSkipPD = false;
    __device__ __forceinline__ void operator()(int, int m, int n, float c) const {
        int hh = n >> 6, i = n & 63;
        g_pos[((size_t)hh*J_ + m)*I_ + i] = c;
    }
};
struct CStorePD {
    static constexpr bool kSkipPD = true;   // tiles with m0+n0<=768 fully dropped
    __device__ __forceinline__ void operator()(int bz, int m, int n, float c) const {
        int j = n + m - 1023;
        if (j >= 0) g_PD[((size_t)bz*S_ + m)*J_ + j] = __float2bfloat16(c);
    }
};
struct CStoreProj {
    static constexpr bool kSkipPD = false;
    const float* x;
    __device__ __forceinline__ void operator()(int, int m, int n, float c) const {
        g_proj[(size_t)m*E_ + n] = c + x[(size_t)m*E_ + n];
    }
};

// ------------------------- mma.sync GEMM (split-bf16) ----------------------
// Round-6 schedule: store chunk -> sync -> prefetch next -> compute -> sync.
constexpr int SROW = 40;   // bf16 elements per smem row (32 data + 8 pad)

template<class AL, class BL, class CS>
__global__ void __launch_bounds__(256)
gemm_mma(AL aload, BL bload, CS cstore, int K) {
    __shared__ __nv_bfloat16 sA[2][128 * SROW];
    __shared__ __nv_bfloat16 sB[2][128 * SROW];

    const int tid  = threadIdx.x;
    const int wid  = tid >> 5;
    const int lane = tid & 31;
    const int gid  = lane >> 2;
    const int tig  = lane & 3;
    const int wm   = wid >> 2;
    const int wn   = wid & 3;
    const int m0   = blockIdx.y * 128;
    const int n0   = blockIdx.x * 128;
    const int bz   = blockIdx.z;

    if constexpr (CS::kSkipPD) {
        if (m0 + n0 <= 768) return;   // all j = n+m-1023 < 0 -> nothing stored
    }

    float c[4][4][4];
#pragma unroll
    for (int mt = 0; mt < 4; mt++)
#pragma unroll
        for (int nt = 0; nt < 4; nt++)
#pragma unroll
            for (int r = 0; r < 4; r++) c[mt][nt][r] = 0.f;

    float4 av[4], bv[4];
#pragma unroll
    for (int q = 0; q < 4; q++) {
        const int f = tid + q * 256, row = f >> 3, kq = (f & 7) * 4;
        av[q] = aload(bz, m0 + row, kq);
        bv[q] = bload(bz, n0 + row, kq);
    }

    for (int k0 = 0; k0 < K; k0 += 32) {
        // ---- store current chunk (split hi/lo) ----
#pragma unroll
        for (int q = 0; q < 4; q++) {
            const int f = tid + q * 256, row = f >> 3, kq = (f & 7) * 4;
            const int so = row * SROW + kq;
            uint32_t h0, l0, h1, l1;
            split2(av[q].x, av[q].y, h0, l0);
            split2(av[q].z, av[q].w, h1, l1);
            *(uint2*)&sA[0][so] = make_uint2(h0, h1);
            *(uint2*)&sA[1][so] = make_uint2(l0, l1);
            split2(bv[q].x, bv[q].y, h0, l0);
            split2(bv[q].z, bv[q].w, h1, l1);
            *(uint2*)&sB[0][so] = make_uint2(h0, h1);
            *(uint2*)&sB[1][so] = make_uint2(l0, l1);
        }
        __syncthreads();

        // ---- prefetch next chunk ----
        if (k0 + 32 < K) {
#pragma unroll
            for (int q = 0; q < 4; q++) {
                const int f = tid + q * 256, row = f >> 3, kq = (f & 7) * 4;
                av[q] = aload(bz, m0 + row, k0 + 32 + kq);
                bv[q] = bload(bz, n0 + row, k0 + 32 + kq);
            }
        }

        // ---- compute ----
#pragma unroll
        for (int ks = 0; ks < 2; ks++) {
            const int kk = ks * 16 + tig * 2;
            uint32_t ah[4][4], al[4][4];
#pragma unroll
            for (int mt = 0; mt < 4; mt++) {
                const int m = wm * 64 + mt * 16 + gid;
                ah[mt][0] = *(const uint32_t*)&sA[0][m * SROW + kk];
                ah[mt][1] = *(const uint32_t*)&sA[0][(m + 8) * SROW + kk];
                ah[mt][2] = *(const uint32_t*)&sA[0][m * SROW + kk + 8];
                ah[mt][3] = *(const uint32_t*)&sA[0][(m + 8) * SROW + kk + 8];
                al[mt][0] = *(const uint32_t*)&sA[1][m * SROW + kk];
                al[mt][1] = *(const uint32_t*)&sA[1][(m + 8) * SROW + kk];
                al[mt][2] = *(const uint32_t*)&sA[1][m * SROW + kk + 8];
                al[mt][3] = *(const uint32_t*)&sA[1][(m + 8) * SROW + kk + 8];
            }
#pragma unroll
            for (int nt = 0; nt < 4; nt++) {
                const int n = wn * 32 + nt * 8 + gid;
                uint32_t bh[2], bl[2];
                bh[0] = *(const uint32_t*)&sB[0][n * SROW + kk];
                bh[1] = *(const uint32_t*)&sB[0][n * SROW + kk + 8];
                bl[0] = *(const uint32_t*)&sB[1][n * SROW + kk];
                bl[1] = *(const uint32_t*)&sB[1][n * SROW + kk + 8];
#pragma unroll
                for (int mt = 0; mt < 4; mt++) {
                    mma_bf16(c[mt][nt], ah[mt], bh);
                    mma_bf16(c[mt][nt], ah[mt], bl);
                    mma_bf16(c[mt][nt], al[mt], bh);
                }
            }
        }
        __syncthreads();
    }

#pragma unroll
    for (int mt = 0; mt < 4; mt++) {
        const int gm = m0 + wm * 64 + mt * 16 + gid;
#pragma unroll
        for (int nt = 0; nt < 4; nt++) {
            const int gn = n0 + wn * 32 + nt * 8 + tig * 2;
            cstore(bz, gm,     gn,     c[mt][nt][0]);
            cstore(bz, gm,     gn + 1, c[mt][nt][1]);
            cstore(bz, gm + 8, gn,     c[mt][nt][2]);
            cstore(bz, gm + 8, gn + 1, c[mt][nt][3]);
        }
    }
}

// ---------------------------- flash attention (MMA) ------------------------
// grid (S/128, B*H), 256 threads = 8 warps; warp wq owns rows wq*16..+15.
// j-tiles of 64. Q/K/Vt pre-split bf16 in gmem; PD bf16 read into fragments.
constexpr int FPAD = 72;   // bf16 elems per smem row (64 data + 8 pad) = 36 words
constexpr int FLASH_SMEM = (128 + 64 + 64) * FPAD * 2 * 2;  // 73728 B

__global__ void __launch_bounds__(256) flash_mma() {
    extern __shared__ __nv_bfloat16 fsm[];
    __nv_bfloat16* sQh = fsm;                    // [s][i] 128x72
    __nv_bfloat16* sQl = sQh + 128 * FPAD;
    __nv_bfloat16* sKh = sQl + 128 * FPAD;       // [j][i] 64x72
    __nv_bfloat16* sKl = sKh + 64 * FPAD;
    __nv_bfloat16* sVh = sKl + 64 * FPAD;        // [i][j] 64x72
    __nv_bfloat16* sVl = sVh + 64 * FPAD;

    const int tid  = threadIdx.x;
    const int wq   = tid >> 5;
    const int lane = tid & 31;
    const int gid  = lane >> 2;
    const int tig  = lane & 3;
    const int s0   = blockIdx.x * 128;
    const int bh   = blockIdx.y;

    const int s_r0 = s0 + wq * 16 + gid;
    const int s_r1 = s_r0 + 8;

    // ---- load Q tile (rows s0..s0+127, 32 words each) ----
    {
        const int row  = tid >> 1;
        const int half = (tid & 1) * 16;                       // word offset
        const uint4* srch = (const uint4*)((const uint32_t*)
            (g_quhi + ((size_t)bh * S_ + s0 + row) * I_) + half);
        const uint4* srcl = (const uint4*)((const uint32_t*)
            (g_qulo + ((size_t)bh * S_ + s0 + row) * I_) + half);
        uint4* dsth = (uint4*)((uint32_t*)&sQh[row * FPAD] + half);
        uint4* dstl = (uint4*)((uint32_t*)&sQl[row * FPAD] + half);
#pragma unroll
        for (int q = 0; q < 4; q++) { dsth[q] = srch[q]; dstl[q] = srcl[q]; }
    }

    const __nv_bfloat16* PDb = g_PD + (size_t)bh * S_ * J_;

    float m_[2] = {-3.0e38f, -3.0e38f};
    float l_[2] = {0.f, 0.f};
    float o[8][4];
#pragma unroll
    for (int nt = 0; nt < 8; nt++)
#pragma unroll
        for (int r = 0; r < 4; r++) o[nt][r] = 0.f;

    const int ntiles = min(32, s0 / 64 + 18);
    for (int jt = 0; jt < ntiles; jt++) {
        const int j0 = jt * 64;
        __syncthreads();
        // ---- load K [j][i] and Vt [i][j] tiles (64 rows x 32 words) ----
        {
            const int row = tid >> 2;
            const int qw  = (tid & 3) * 8;                     // word offset
            const uint32_t* kh = (const uint32_t*)
                (g_Khi + (((size_t)bh * J_) + j0 + row) * I_) + qw;
            const uint32_t* kl = (const uint32_t*)
                (g_Klo + (((size_t)bh * J_) + j0 + row) * I_) + qw;
            const uint32_t* vh = (const uint32_t*)
                (g_Vthi + ((size_t)bh * I_ + row) * J_ + j0) + qw;
            const uint32_t* vl = (const uint32_t*)
                (g_Vtlo + ((size_t)bh * I_ + row) * J_ + j0) + qw;
            uint32_t* dkh = (uint32_t*)&sKh[row * FPAD] + qw;
            uint32_t* dkl = (uint32_t*)&sKl[row * FPAD] + qw;
            uint32_t* dvh = (uint32_t*)&sVh[row * FPAD] + qw;
            uint32_t* dvl = (uint32_t*)&sVl[row * FPAD] + qw;
            *(uint4*)dkh = *(const uint4*)kh;  *(uint4*)(dkh+4) = *(const uint4*)(kh+4);
            *(uint4*)dkl = *(const uint4*)kl;  *(uint4*)(dkl+4) = *(const uint4*)(kl+4);
            *(uint4*)dvh = *(const uint4*)vh;  *(uint4*)(dvh+4) = *(const uint4*)(vh+4);
            *(uint4*)dvl = *(const uint4*)vl;  *(uint4*)(dvl+4) = *(const uint4*)(vl+4);
        }
        __syncthreads();

        // ---- scores S = Q @ K^T (128x64 per block, 16x64 per warp) ----
        float sc[8][4];
#pragma unroll
        for (int nt = 0; nt < 8; nt++)
#pragma unroll
            for (int r = 0; r < 4; r++) sc[nt][r] = 0.f;

        const uint32_t* qh32 = (const uint32_t*)sQh;
        const uint32_t* ql32 = (const uint32_t*)sQl;
        const uint32_t* kh32 = (const uint32_t*)sKh;
        const uint32_t* kl32 = (const uint32_t*)sKl;
        const int r0w = (wq * 16 + gid) * (FPAD/2);
        const int r1w = r0w + 8 * (FPAD/2);
#pragma unroll
        for (int ks = 0; ks < 4; ks++) {
            const int w = ks * 8 + tig;
            uint32_t ah[4], al[4];
            ah[0] = qh32[r0w + w];     ah[1] = qh32[r1w + w];
            ah[2] = qh32[r0w + w + 4]; ah[3] = qh32[r1w + w + 4];
            al[0] = ql32[r0w + w];     al[1] = ql32[r1w + w];
            al[2] = ql32[r0w + w + 4]; al[3] = ql32[r1w + w + 4];
#pragma unroll
            for (int nt = 0; nt < 8; nt++) {
                const int nw = (nt * 8 + gid) * (FPAD/2);
                uint32_t bh2[2] = { kh32[nw + w], kh32[nw + w + 4] };
                uint32_t bl2[2] = { kl32[nw + w], kl32[nw + w + 4] };
                mma_bf16(sc[nt], ah, bh2);
                mma_bf16(sc[nt], ah, bl2);
                mma_bf16(sc[nt], al, bh2);
            }
        }

        // ---- + PD (bf16), mask, scale ----
#pragma unroll
        for (int nt = 0; nt < 8; nt++) {
            const int jc = j0 + nt * 8 + tig * 2;
            __nv_bfloat162 p0 = *(const __nv_bfloat162*)&PDb[(size_t)s_r0 * J_ + jc];
            __nv_bfloat162 p1 = *(const __nv_bfloat162*)&PDb[(size_t)s_r1 * J_ + jc];
            sc[nt][0] = (jc     <= s_r0 + P_)
                        ? (sc[nt][0] + __bfloat162float(p0.x)) * SCALE_ : -1.0e30f;
            sc[nt][1] = (jc + 1 <= s_r0 + P_)
                        ? (sc[nt][1] + __bfloat162float(p0.y)) * SCALE_ : -1.0e30f;
            sc[nt][2] = (jc     <= s_r1 + P_)
                        ? (sc[nt][2] + __bfloat162float(p1.x)) * SCALE_ : -1.0e30f;
            sc[nt][3] = (jc + 1 <= s_r1 + P_)
                        ? (sc[nt][3] + __bfloat162float(p1.y)) * SCALE_ : -1.0e30f;
        }

        // ---- online softmax (rows r0: idx 0,1; r1: idx 2,3) ----
#pragma unroll
        for (int h = 0; h < 2; h++) {
            float mx = -3.0e38f;
#pragma unroll
            for (int nt = 0; nt < 8; nt++)
                mx = fmaxf(mx, fmaxf(sc[nt][2*h], sc[nt][2*h+1]));
            mx = fmaxf(mx, __shfl_xor_sync(0xffffffffu, mx, 1));
            mx = fmaxf(mx, __shfl_xor_sync(0xffffffffu, mx, 2));
            const float m_new = fmaxf(m_[h], mx);
            const float corr  = __expf(m_[h] - m_new);
            float sum = 0.f;
#pragma unroll
            for (int nt = 0; nt < 8; nt++) {
                float p0 = __expf(sc[nt][2*h]   - m_new);
                float p1 = __expf(sc[nt][2*h+1] - m_new);
                sc[nt][2*h] = p0; sc[nt][2*h+1] = p1;
                sum += p0 + p1;
            }
            sum += __shfl_xor_sync(0xffffffffu, sum, 1);
            sum += __shfl_xor_sync(0xffffffffu, sum, 2);
            l_[h] = l_[h] * corr + sum;
            m_[h] = m_new;
#pragma unroll
            for (int nt = 0; nt < 8; nt++) {
                o[nt][2*h]   *= corr;
                o[nt][2*h+1] *= corr;
            }
        }

        // ---- O += P @ V (P fragments from scores, V^T as B) ----
        const uint32_t* vh32 = (const uint32_t*)sVh;
        const uint32_t* vl32 = (const uint32_t*)sVl;
#pragma unroll
        for (int ks = 0; ks < 4; ks++) {
            uint32_t ph[4], pl[4];
            split2(sc[2*ks][0],   sc[2*ks][1],   ph[0], pl[0]);
            split2(sc[2*ks][2],   sc[2*ks][3],   ph[1], pl[1]);
            split2(sc[2*ks+1][0], sc[2*ks+1][1], ph[2], pl[2]);
            split2(sc[2*ks+1][2], sc[2*ks+1][3], ph[3], pl[3]);
            const int w = ks * 8 + tig;
#pragma unroll
            for (int nt = 0; nt < 8; nt++) {
                const int nw = (nt * 8 + gid) * (FPAD/2);
                uint32_t bh2[2] = { vh32[nw + w], vh32[nw + w + 4] };
                uint32_t bl2[2] = { vl32[nw + w], vl32[nw + w + 4] };
                mma_bf16(o[nt], ph, bh2);
                mma_bf16(o[nt], ph, bl2);
                mma_bf16(o[nt], pl, bh2);
            }
        }
    }

    // ---- epilogue: ctx[(s,b)][h*64+i] ----
    const float inv0 = 1.f / l_[0];
    const float inv1 = 1.f / l_[1];
    const int b = bh >> 4, hh = bh & 15;
#pragma unroll
    for (int nt = 0; nt < 8; nt++) {
        const int ic = hh * 64 + nt * 8 + tig * 2;
        *(float2*)&g_ctx[((size_t)(s_r0 * B_ + b)) * HI_ + ic] =
            make_float2(o[nt][0] * inv0, o[nt][1] * inv0);
        *(float2*)&g_ctx[((size_t)(s_r1 * B_ + b)) * HI_ + ic] =
            make_float2(o[nt][2] * inv1, o[nt][3] * inv1);
    }
}

// ------------------------------ layernorm ----------------------------------
__device__ __forceinline__ float warp_red_sum(float v) {
#pragma unroll
    for (int o = 16; o; o >>= 1) v += __shfl_xor_sync(0xffffffffu, v, o);
    return v;
}
__global__ void __launch_bounds__(256)
ln_kernel(const float* __restrict__ gamma, const float* __restrict__ beta,
          float* __restrict__ out) {
    const int row = blockIdx.x;
    const int tid = threadIdx.x;
    const float* p = g_proj + (size_t)row * E_;
    __shared__ float red[8];

    float v[4];
    float s = 0.f;
#pragma unroll
    for (int t = 0; t < 4; t++) { v[t] = p[tid + t*256]; s += v[t]; }
    s = warp_red_sum(s);
    if ((tid & 31) == 0) red[tid >> 5] = s;
    __syncthreads();
    float tot = 0.f;
#pragma unroll
    for (int w = 0; w < 8; w++) tot += red[w];
    const float mu = tot * (1.0f / E_);

    float vs = 0.f;
#pragma unroll
    for (int t = 0; t < 4; t++) { float d = v[t] - mu; vs += d * d; }
    vs = warp_red_sum(vs);
    __syncthreads();
    if ((tid & 31) == 0) red[tid >> 5] = vs;
    __syncthreads();
    float vtot = 0.f;
#pragma unroll
    for (int w = 0; w < 8; w++) vtot += red[w];
    const float inv = rsqrtf(vtot * (1.0f / E_) + EPS_);

#pragma unroll
    for (int t = 0; t < 4; t++) {
        int e = tid + t*256;
        out[(size_t)row * E_ + e] = (v[t] - mu) * inv * gamma[e] + beta[e];
    }
}

// ------------------------------- launch ------------------------------------
extern "C" void kernel_launch(void* const* d_in, const int* in_sizes, int n_in,
                              void* d_out, int out_size) {
    (void)in_sizes; (void)n_in; (void)out_size;
    const float* x     = (const float*)d_in[0];
    const float* rel   = (const float*)d_in[1];
    const float* mem   = (const float*)d_in[2];
    const float* u     = (const float*)d_in[3];
    const float* v     = (const float*)d_in[4];
    const float* Wkv   = (const float*)d_in[6];
    const float* Wq    = (const float*)d_in[7];
    const float* Wp    = (const float*)d_in[8];
    const float* Wo    = (const float*)d_in[9];
    const float* gamma = (const float*)d_in[10];
    const float* beta  = (const float*)d_in[11];
    float* out = (float*)d_out;

    // unconditional (no static guards); attribute call is capture-safe
    cudaFuncSetAttribute(flash_mma,
                         cudaFuncAttributeMaxDynamicSharedMemorySize, FLASH_SMEM);

    // 1. kv projection -> Khi/Klo, Vthi/Vtlo (split bf16, V transposed)
    gemm_mma<<<dim3(2*HI_/128, J_*B_/128, 1), 256>>>(
        ALoadKV{mem, x}, BLoadW{Wkv, E_}, CStoreKV{}, E_);

    // 2. q projection -> quhi/qulo (+u), qv fp32 (+v)
    gemm_mma<<<dim3(HI_/128, S_*B_/128, 1), 256>>>(
        ALoadPlain{x, E_}, BLoadW{Wq, E_}, CStoreQ{u, v}, E_);

    // 3. pos projection (fp32)
    gemm_mma<<<dim3(HI_/128, J_/128, 1), 256>>>(
        ALoadPlain{rel, E_}, BLoadW{Wp, E_}, CStorePos{}, E_);

    // 4. PD (pre-shifted store, bf16, tile early-exit)
    gemm_mma<<<dim3(J_/128, S_/128, B_*H_), 256>>>(
        ALoadQV{}, BLoadPos{}, CStorePD{}, I_);

    // 5. flash attention (tensor cores) -> ctx
    flash_mma<<<dim3(S_/128, B_*H_), 256, FLASH_SMEM>>>();

    // 6. out projection + residual
    gemm_mma<<<dim3(E_/128, S_*B_/128, 1), 256>>>(
        ALoadCtx{}, BLoadW{Wo, HI_}, CStoreProj{x}, HI_);

    // 7. layernorm
    ln_kernel<<<S_*B_, 256>>>(gamma, beta, out);
}